// round 4
// baseline (speedup 1.0000x reference)
#include <cuda_runtime.h>
#include <cuda_bf16.h>
#include <math.h>
#include <stdint.h>

#define NBn 65536
#define EE  1048576
#define Bg  128
#define Ng  512
#define Fd  128
#define KP1 410
#define KP2 205
#define KP3 103

#define FINF __int_as_float(0x7f800000)

// ================= mma.sync helpers (baseline PTX, no sm_103a features) =================
__device__ __forceinline__ uint32_t smem_u32(const void* p) {
    uint32_t a;
    asm("{ .reg .u64 t; cvta.to.shared.u64 t, %1; cvt.u32.u64 %0, t; }" : "=r"(a) : "l"(p));
    return a;
}
__device__ __forceinline__ void ldsm4(uint32_t a, uint32_t& r0, uint32_t& r1, uint32_t& r2, uint32_t& r3) {
    asm volatile("ldmatrix.sync.aligned.m8n8.x4.shared.b16 {%0,%1,%2,%3}, [%4];"
        : "=r"(r0), "=r"(r1), "=r"(r2), "=r"(r3) : "r"(a));
}
__device__ __forceinline__ void ldsm4t(uint32_t a, uint32_t& r0, uint32_t& r1, uint32_t& r2, uint32_t& r3) {
    asm volatile("ldmatrix.sync.aligned.m8n8.x4.trans.shared.b16 {%0,%1,%2,%3}, [%4];"
        : "=r"(r0), "=r"(r1), "=r"(r2), "=r"(r3) : "r"(a));
}
__device__ __forceinline__ void mma16816(float* d, const uint32_t* a, uint32_t b0, uint32_t b1) {
    asm volatile("mma.sync.aligned.m16n8k16.row.col.f32.bf16.bf16.f32 "
        "{%0,%1,%2,%3},{%4,%5,%6,%7},{%8,%9},{%0,%1,%2,%3};"
        : "+f"(d[0]), "+f"(d[1]), "+f"(d[2]), "+f"(d[3])
        : "r"(a[0]), "r"(a[1]), "r"(a[2]), "r"(a[3]), "r"(b0), "r"(b1));
}

// swizzled smem offset: 128 rows x 16 chunks of 16B (256B/row), XOR swizzle kills bank conflicts
#define SW_OFF(r, c) ((uint32_t)((r) * 256 + ((((c) ^ ((r) & 7))) << 4)))

// ================= device scratch =================
__device__ __align__(16) float d_x[NBn * Fd];
__device__ __align__(16) float d_y[NBn * Fd];
__device__ __align__(16) float d_agg[NBn * Fd];
__device__ __align__(16) float d_xs[NBn * Fd];
__device__ float d_score[NBn];
__device__ float d_nmask[NBn];
__device__ float d_emf[EE];
__device__ int   d_indeg[NBn];
__device__ int   d_off[NBn + 1];
__device__ int   d_fill[NBn];
__device__ int   d_eid[EE];
__device__ float d_als[NBn * 4];
__device__ float d_ald[NBn * 4];
__device__ float d_ale[EE * 4];
__device__ float d_weeff[28];
__device__ float d_alse[4];
__device__ float d_eamean[8];
__device__ float d_pinv;
__device__ float d_r[NBn];
__device__ float d_q[NBn];
__device__ float d_g1[Bg * Fd];
__device__ float d_g2[Bg * Fd];
__device__ float d_g3[Bg * Fd];
// 5 weight matrices, each: hi bf16 32KB + lo bf16 32KB, SW-swizzled [k][n]
__device__ __align__(16) unsigned char d_wbf[5 * 65536];

// ================= helpers =================
__device__ __forceinline__ float warp_red(float v) {
    #pragma unroll
    for (int o = 16; o; o >>= 1) v += __shfl_down_sync(0xffffffffu, v, o);
    return v;
}

// ================= init =================
__global__ void init_k() {
    int t = blockIdx.x * blockDim.x + threadIdx.x;
    if (t < EE) d_emf[t] = 1.0f;
    if (t < NBn) { d_nmask[t] = 1.0f; d_indeg[t] = 0; d_fill[t] = 0; }
    if (t < 8) d_eamean[t] = 0.0f;
    if (t < Bg * Fd) { d_g1[t] = 0.f; d_g2[t] = 0.f; d_g3[t] = 0.f; }
}

// ================= CSR build =================
__global__ void csr_count_k(const int* __restrict__ dst) {
    int e = blockIdx.x * blockDim.x + threadIdx.x;
    if (e < EE) atomicAdd(&d_indeg[dst[e]], 1);
}
__global__ void scan_k() {
    __shared__ int tot[512];
    int t = threadIdx.x;
    int base = t * 128;
    int s = 0;
    for (int j = 0; j < 128; j++) { d_off[base + j] = s; s += d_indeg[base + j]; }
    tot[t] = s;
    __syncthreads();
    if (t == 0) {
        int run = 0;
        for (int k = 0; k < 512; k++) { int v = tot[k]; tot[k] = run; run += v; }
        d_off[NBn] = run;
    }
    __syncthreads();
    int add = tot[t];
    for (int j = 0; j < 128; j++) d_off[base + j] += add;
}
__global__ void csr_fill_k(const int* __restrict__ dst) {
    int e = blockIdx.x * blockDim.x + threadIdx.x;
    if (e < EE) {
        int d = dst[e];
        int p = atomicAdd(&d_fill[d], 1);
        d_eid[d_off[d] + p] = e;
    }
}

// ================= p1 norm =================
__global__ void norm_k(const float* __restrict__ pw) {
    __shared__ float r[128];
    int t = threadIdx.x;
    float v = pw[t];
    r[t] = v * v;
    __syncthreads();
    for (int o = 64; o; o >>= 1) { if (t < o) r[t] += r[t + o]; __syncthreads(); }
    if (t == 0) d_pinv = rsqrtf(r[0]);
}

// ================= weight prep: fp32 -> bf16 hi/lo, SW-swizzled [k][n] =================
__global__ void prep_w_k(const float* __restrict__ w0, const float* __restrict__ w1,
                         const float* __restrict__ w2, const float* __restrict__ w3,
                         const float* __restrict__ w4) {
    int id = blockIdx.x * blockDim.x + threadIdx.x;
    if (id >= 5 * 16384) return;
    int m = id >> 14;
    int r = id & 16383;
    int k = r >> 7, n = r & 127;
    const float* W = (m == 0) ? w0 : (m == 1) ? w1 : (m == 2) ? w2 : (m == 3) ? w3 : w4;
    float f = W[k * 128 + n];
    __nv_bfloat16 hb = __float2bfloat16(f);
    __nv_bfloat16 lb = __float2bfloat16(f - __bfloat162float(hb));
    uint32_t off = SW_OFF(k, n >> 3) + (uint32_t)(n & 7) * 2;
    unsigned char* base = d_wbf + m * 65536;
    *(__nv_bfloat16*)(base + off) = hb;
    *(__nv_bfloat16*)(base + 32768 + off) = lb;
}

// ================= HMMA GEMM: C[128x128/CTA] = A1@W1 (+A2@W2) (+bias)(relu) =================
// bf16 hi/lo split, 3 cross products per input. 256 thr, warp grid 2(m)x4(n), warp tile 64x32.
__device__ __forceinline__ void stageA(const float* __restrict__ A, int bm, char* smA, int tid) {
    for (int i = tid; i < 2048; i += 256) {
        int r = i >> 4, c = i & 15;
        const float4* s = (const float4*)(A + (size_t)(bm + r) * 128 + c * 8);
        float4 f0 = s[0], f1 = s[1];
        float v[8] = {f0.x, f0.y, f0.z, f0.w, f1.x, f1.y, f1.z, f1.w};
        __nv_bfloat16 h[8], l[8];
        #pragma unroll
        for (int j = 0; j < 8; j++) {
            h[j] = __float2bfloat16(v[j]);
            l[j] = __float2bfloat16(v[j] - __bfloat162float(h[j]));
        }
        uint32_t off = SW_OFF(r, c);
        *(uint4*)(smA + off) = *(uint4*)h;
        *(uint4*)(smA + 32768 + off) = *(uint4*)l;
    }
}

__device__ __noinline__ void hmma_pass(uint32_t aS, uint32_t bS, int wm, int wn, int lane,
                                       float (*acc)[4][4]) {
    int lr = lane & 15, lc = lane >> 4;
    #pragma unroll
    for (int ks = 0; ks < 8; ks++) {
        uint32_t a[4][4];
        #pragma unroll
        for (int mi = 0; mi < 4; mi++) {
            int row = wm * 64 + mi * 16 + lr;
            int ch = ks * 2 + lc;
            ldsm4(aS + SW_OFF(row, ch), a[mi][0], a[mi][1], a[mi][2], a[mi][3]);
        }
        uint32_t b[2][4];
        #pragma unroll
        for (int nb = 0; nb < 2; nb++) {
            int row = ks * 16 + lr;
            int ch = wn * 4 + nb * 2 + lc;
            ldsm4t(bS + SW_OFF(row, ch), b[nb][0], b[nb][1], b[nb][2], b[nb][3]);
        }
        #pragma unroll
        for (int mi = 0; mi < 4; mi++)
            #pragma unroll
            for (int ni = 0; ni < 4; ni++)
                mma16816(acc[mi][ni], a[mi], b[ni >> 1][(ni & 1) * 2], b[ni >> 1][(ni & 1) * 2 + 1]);
    }
}

__global__ void __launch_bounds__(256, 1) tgemm_k(
    const float* __restrict__ A1, const unsigned char* __restrict__ W1,
    const float* __restrict__ A2, const unsigned char* __restrict__ W2,
    const float* __restrict__ bias, float* __restrict__ C, int relu)
{
    extern __shared__ char sm[];
    uint32_t sb = smem_u32(sm);
    int tid = threadIdx.x, lane = tid & 31, wid = tid >> 5;
    int wm = wid & 1, wn = wid >> 1;
    int bm = blockIdx.x * 128;
    const uint32_t Ahi = sb, Alo = sb + 32768, Whi = sb + 65536, Wlo = sb + 98304;
    float acc[4][4][4] = {};

    // ---- phase 0 ----
    stageA(A1, bm, sm, tid);
    {
        uint4* dW = (uint4*)(sm + 65536);
        const uint4* sW = (const uint4*)W1;
        for (int i = tid; i < 4096; i += 256) dW[i] = sW[i];   // hi+lo contiguous 64KB
    }
    __syncthreads();
    {
        uint32_t pa[3] = {Ahi, Ahi, Alo};
        uint32_t pb[3] = {Whi, Wlo, Whi};
        #pragma unroll 1
        for (int p = 0; p < 3; p++) hmma_pass(pa[p], pb[p], wm, wn, lane, acc);
    }
    // ---- phase 1 (fused second matmul accumulating into same regs) ----
    if (A2) {
        __syncthreads();
        stageA(A2, bm, sm, tid);
        {
            uint4* dW = (uint4*)(sm + 65536);
            const uint4* sW = (const uint4*)W2;
            for (int i = tid; i < 4096; i += 256) dW[i] = sW[i];
        }
        __syncthreads();
        uint32_t pa[3] = {Ahi, Ahi, Alo};
        uint32_t pb[3] = {Whi, Wlo, Whi};
        #pragma unroll 1
        for (int p = 0; p < 3; p++) hmma_pass(pa[p], pb[p], wm, wn, lane, acc);
    }

    // ---- epilogue ----
    int group = lane >> 2, tig = lane & 3;
    #pragma unroll
    for (int mi = 0; mi < 4; mi++) {
        int row = bm + wm * 64 + mi * 16 + group;
        #pragma unroll
        for (int ni = 0; ni < 4; ni++) {
            int col = wn * 32 + ni * 8 + tig * 2;
            float b0 = 0.f, b1 = 0.f;
            if (bias) { b0 = bias[col]; b1 = bias[col + 1]; }
            float2 v0 = make_float2(acc[mi][ni][0] + b0, acc[mi][ni][1] + b1);
            float2 v1 = make_float2(acc[mi][ni][2] + b0, acc[mi][ni][3] + b1);
            if (relu) {
                v0.x = fmaxf(v0.x, 0.f); v0.y = fmaxf(v0.y, 0.f);
                v1.x = fmaxf(v1.x, 0.f); v1.y = fmaxf(v1.y, 0.f);
            }
            *(float2*)(C + (size_t)row * 128 + col) = v0;
            *(float2*)(C + (size_t)(row + 8) * 128 + col) = v1;
        }
    }
}
#define TGEMM_SMEM 131072

// ================= segment mean aggregation via CSR (warp per dst) =================
__global__ void agg_k(const float* __restrict__ x, const int* __restrict__ srcA) {
    int warp = (blockIdx.x * blockDim.x + threadIdx.x) >> 5;
    if (warp >= NBn) return;
    int lane = threadIdx.x & 31;
    int beg = d_off[warp], end = d_off[warp + 1];
    float4 acc = make_float4(0.f, 0.f, 0.f, 0.f);
    float cnt = 0.f;
    for (int j = beg; j < end; j++) {
        int e = d_eid[j];
        float m = d_emf[e];
        if (m != 0.f) {
            int s = srcA[e];
            float4 v = *reinterpret_cast<const float4*>(x + (size_t)s * Fd + lane * 4);
            acc.x += v.x; acc.y += v.y; acc.z += v.z; acc.w += v.w;
            cnt += 1.f;
        }
    }
    float inv = 1.f / fmaxf(cnt, 1.f);
    acc.x *= inv; acc.y *= inv; acc.z *= inv; acc.w *= inv;
    *reinterpret_cast<float4*>(d_agg + (size_t)warp * Fd + lane * 4) = acc;
}

// ================= scores =================
__global__ void score1_k(const float* __restrict__ pw) {
    int warp = (blockIdx.x * blockDim.x + threadIdx.x) >> 5;
    if (warp >= NBn) return;
    int lane = threadIdx.x & 31;
    float s = 0.f;
    #pragma unroll
    for (int q = 0; q < 4; q++) {
        int f = lane + 32 * q;
        s += d_x[(size_t)warp * Fd + f] * pw[f];
    }
    s = warp_red(s);
    if (lane == 0) d_score[warp] = tanhf(s * d_pinv);
}

// per-node scalar dots r = x.wrel, q = x.wroot
__global__ void dot2_k(const float* __restrict__ x, const float* __restrict__ wrel,
                       const float* __restrict__ wroot) {
    int warp = (blockIdx.x * blockDim.x + threadIdx.x) >> 5;
    if (warp >= NBn) return;
    int lane = threadIdx.x & 31;
    float s1 = 0.f, s2 = 0.f;
    #pragma unroll
    for (int q = 0; q < 4; q++) {
        int f = lane + 32 * q;
        float v = x[(size_t)warp * Fd + f];
        s1 += v * wrel[f];
        s2 += v * wroot[f];
    }
    s1 = warp_red(s1); s2 = warp_red(s2);
    if (lane == 0) { d_r[warp] = s1; d_q[warp] = s2; }
}

// scalar CSR aggregation for SAG score (thread per dst)
__global__ void sag2b_k(const int* __restrict__ srcA, const float* __restrict__ brel) {
    int i = blockIdx.x * blockDim.x + threadIdx.x;
    if (i >= NBn) return;
    int beg = d_off[i], end = d_off[i + 1];
    float s = 0.f;
    for (int j = beg; j < end; j++) {
        int e = d_eid[j];
        if (d_emf[e] != 0.f) s += d_r[srcA[e]];
    }
    d_score[i] = tanhf(s + d_q[i] + brel[0]);
}

// ================= top-K pooling =================
__global__ void pool_k(int K) {
    __shared__ float sv[512];
    __shared__ short si[512];
    int g = blockIdx.x, t = threadIdx.x;
    for (int p = t; p < 512; p += 256) {
        int node = g * Ng + p;
        sv[p] = (d_nmask[node] != 0.f) ? d_score[node] : -FINF;
        si[p] = (short)p;
    }
    __syncthreads();
    for (int k = 2; k <= 512; k <<= 1) {
        for (int j = k >> 1; j > 0; j >>= 1) {
            for (int p = t; p < 512; p += 256) {
                int ixj = p ^ j;
                if (ixj > p) {
                    float v1 = sv[p], v2 = sv[ixj];
                    short i1 = si[p], i2 = si[ixj];
                    bool beforePI = (v1 > v2) || (v1 == v2 && i1 < i2);
                    bool dir = ((p & k) == 0);
                    if (dir ? !beforePI : beforePI) {
                        sv[p] = v2; sv[ixj] = v1;
                        si[p] = i2; si[ixj] = i1;
                    }
                }
            }
            __syncthreads();
        }
    }
    for (int p = t; p < 512; p += 256)
        d_nmask[g * Ng + si[p]] = (p < K) ? 1.f : 0.f;
}

__global__ void apply_pool_k(float* __restrict__ x) {
    int id = blockIdx.x * blockDim.x + threadIdx.x;
    int node = id >> 5, q = id & 31;
    float sc = d_nmask[node] * d_score[node];
    float4* p = reinterpret_cast<float4*>(x + (size_t)node * Fd + q * 4);
    float4 v = *p;
    v.x *= sc; v.y *= sc; v.z *= sc; v.w *= sc;
    *p = v;
}

__global__ void emf_update_k(const int* __restrict__ srcA, const int* __restrict__ dstA) {
    int e = blockIdx.x * blockDim.x + threadIdx.x;
    if (e < EE) d_emf[e] = d_nmask[srcA[e]] * d_nmask[dstA[e]];
}

__global__ void gap_k(const float* __restrict__ x, float* __restrict__ outg, float invK) {
    int b = blockIdx.x;                  // Bg*4 blocks x 128 threads
    int g = b >> 2, part = b & 3, f = threadIdx.x;
    float s = 0.f;
    int base = g * Ng + part * 128;
    for (int n = 0; n < 128; n++) s += x[(size_t)(base + n) * Fd + f];
    atomicAdd(&outg[g * Fd + f], s * invK);
}

// ================= GAT =================
__global__ void alsald_k(const float* __restrict__ as_, const float* __restrict__ ad_) {
    int warp = (blockIdx.x * blockDim.x + threadIdx.x) >> 5;
    if (warp >= NBn) return;
    int lane = threadIdx.x & 31;
    #pragma unroll
    for (int h = 0; h < 4; h++) {
        float v = d_xs[(size_t)warp * Fd + h * 32 + lane];
        float ps = v * as_[h * 32 + lane];
        float pd = v * ad_[h * 32 + lane];
        ps = warp_red(ps); pd = warp_red(pd);
        if (lane == 0) { d_als[warp * 4 + h] = ps; d_ald[warp * 4 + h] = pd; }
    }
}

__global__ void weeff_k(const float* __restrict__ g_we, const float* __restrict__ a_e) {
    int t = threadIdx.x;
    if (t < 28) {
        int d = t >> 2, h = t & 3;
        float s = 0.f;
        for (int c = 0; c < 32; c++) s += g_we[d * 128 + h * 32 + c] * a_e[h * 32 + c];
        d_weeff[d * 4 + h] = s;
    }
}

__global__ void ale_k(const float* __restrict__ ea) {
    int e = blockIdx.x * blockDim.x + threadIdx.x;
    if (e >= EE) return;
    float a[7];
    #pragma unroll
    for (int d = 0; d < 7; d++) a[d] = ea[(size_t)e * 7 + d];
    #pragma unroll
    for (int h = 0; h < 4; h++) {
        float s = 0.f;
        #pragma unroll
        for (int d = 0; d < 7; d++) s += a[d] * d_weeff[d * 4 + h];
        d_ale[(size_t)e * 4 + h] = s;
    }
}

__global__ void eamean_k(const float* __restrict__ ea) {
    __shared__ float red[256 * 8];
    int t = threadIdx.x;
    float acc[7] = {}; float c = 0.f;
    for (int e = blockIdx.x * 256 + t; e < EE; e += gridDim.x * 256) {
        float m = d_emf[e];
        if (m != 0.f) {
            #pragma unroll
            for (int d = 0; d < 7; d++) acc[d] += ea[(size_t)e * 7 + d];
            c += 1.f;
        }
    }
    #pragma unroll
    for (int d = 0; d < 7; d++) red[t * 8 + d] = acc[d];
    red[t * 8 + 7] = c;
    __syncthreads();
    if (t < 8) {
        float s = 0.f;
        for (int j = 0; j < 256; j++) s += red[j * 8 + t];
        atomicAdd(&d_eamean[t], s);
    }
}

__global__ void alse_k() {
    int h = threadIdx.x;
    if (h < 4) {
        float cnt = fmaxf(d_eamean[7], 1.f);
        float s = 0.f;
        for (int d = 0; d < 7; d++) s += (d_eamean[d] / cnt) * d_weeff[d * 4 + h];
        d_alse[h] = s;
    }
}

__device__ __forceinline__ float lrelu(float a) { return a > 0.f ? a : 0.2f * a; }

__global__ void gat_k(const int* __restrict__ srcA, const float* __restrict__ gb) {
    int i = blockIdx.x, t = threadIdx.x;
    __shared__ float sm[4], sden[4];
    __shared__ float red[128 * 4];
    __shared__ float s_w[32 * 4];
    __shared__ int s_src[32];
    __shared__ float s_ald[4], s_alsi[4];
    int beg = d_off[i], end = d_off[i + 1];
    if (t < 4) { s_ald[t] = d_ald[i * 4 + t]; s_alsi[t] = d_als[i * 4 + t]; }
    __syncthreads();
    float mx0 = -FINF, mx1 = -FINF, mx2 = -FINF, mx3 = -FINF;
    for (int j = beg + t; j < end; j += 128) {
        int e = d_eid[j];
        if (d_emf[e] != 0.f) {
            int s = srcA[e];
            mx0 = fmaxf(mx0, lrelu(d_als[s * 4 + 0] + s_ald[0] + d_ale[(size_t)e * 4 + 0]));
            mx1 = fmaxf(mx1, lrelu(d_als[s * 4 + 1] + s_ald[1] + d_ale[(size_t)e * 4 + 1]));
            mx2 = fmaxf(mx2, lrelu(d_als[s * 4 + 2] + s_ald[2] + d_ale[(size_t)e * 4 + 2]));
            mx3 = fmaxf(mx3, lrelu(d_als[s * 4 + 3] + s_ald[3] + d_ale[(size_t)e * 4 + 3]));
        }
    }
    red[t * 4 + 0] = mx0; red[t * 4 + 1] = mx1; red[t * 4 + 2] = mx2; red[t * 4 + 3] = mx3;
    __syncthreads();
    if (t < 4) {
        float m = -FINF;
        for (int j = 0; j < 128; j++) m = fmaxf(m, red[j * 4 + t]);
        if (d_nmask[i] != 0.f)
            m = fmaxf(m, lrelu(s_alsi[t] + s_ald[t] + d_alse[t]));
        if (!isfinite(m)) m = 0.f;
        sm[t] = m; sden[t] = 0.f;
    }
    __syncthreads();
    float acc = 0.f;
    int h = t >> 5;
    for (int cb = beg; cb < end; cb += 32) {
        int n = min(32, end - cb);
        int jl = t >> 2, hh = t & 3;
        if (jl < n) {
            int e = d_eid[cb + jl];
            int s = srcA[e];
            if (hh == 0) s_src[jl] = s;
            float w = 0.f;
            if (d_emf[e] != 0.f) {
                float a = lrelu(d_als[s * 4 + hh] + s_ald[hh] + d_ale[(size_t)e * 4 + hh]);
                w = __expf(a - sm[hh]);
            }
            s_w[jl * 4 + hh] = w;
        }
        __syncthreads();
        if (t < 4) {
            float s = 0.f;
            for (int j = 0; j < n; j++) s += s_w[j * 4 + t];
            sden[t] += s;
        }
        for (int j = 0; j < n; j++)
            acc += s_w[j * 4 + h] * d_xs[(size_t)s_src[j] * Fd + t];
        __syncthreads();
    }
    if (d_nmask[i] != 0.f) {
        float a = lrelu(s_alsi[h] + s_ald[h] + d_alse[h]);
        acc += __expf(a - sm[h]) * d_xs[(size_t)i * Fd + t];
        if (t < 4) {
            float a4 = lrelu(s_alsi[t] + s_ald[t] + d_alse[t]);
            sden[t] += __expf(a4 - sm[t]);
        }
    }
    __syncthreads();
    float den = fmaxf(sden[h], 1e-16f);
    d_x[(size_t)i * Fd + t] = fmaxf(acc / den + gb[t], 0.f);
}

// ================= final MLP head =================
__global__ void mlp_k(const float* __restrict__ l1w, const float* __restrict__ l1b,
                      const float* __restrict__ l2w, const float* __restrict__ l2b,
                      const float* __restrict__ l3w, const float* __restrict__ l3b,
                      float* __restrict__ out) {
    int g = blockIdx.x, t = threadIdx.x;
    __shared__ float h0[128], t1[128], t2[64], rr[64];
    h0[t] = d_g1[g * Fd + t] + d_g2[g * Fd + t] + d_g3[g * Fd + t];
    __syncthreads();
    float s = 0.f;
    for (int k = 0; k < 128; k++) s += h0[k] * l1w[k * 128 + t];
    t1[t] = fmaxf(s + l1b[t], 0.f);
    __syncthreads();
    if (t < 64) {
        float s2 = 0.f;
        for (int k = 0; k < 128; k++) s2 += t1[k] * l2w[k * 64 + t];
        t2[t] = fmaxf(s2 + l2b[t], 0.f);
        rr[t] = 0.f;
    }
    __syncthreads();
    if (t < 64) rr[t] = t2[t] * l3w[t];
    __syncthreads();
    for (int o = 32; o; o >>= 1) { if (t < o) rr[t] += rr[t + o]; __syncthreads(); }
    if (t == 0) out[g] = 1.f / (1.f + expf(-(rr[0] + l3b[0])));
}

// ================= host =================
extern "C" void kernel_launch(void* const* d_in, const int* in_sizes, int n_in,
                              void* d_out, int out_size) {
    const float* x_in  = (const float*)d_in[0];
    const int*   ei    = (const int*)d_in[1];
    const int*   srcA  = ei;
    const int*   dstA  = ei + EE;
    const float* ea    = (const float*)d_in[2];
    const float* c1_wl = (const float*)d_in[3];
    const float* c1_bl = (const float*)d_in[4];
    const float* c1_wr = (const float*)d_in[5];
    const float* p1_w  = (const float*)d_in[6];
    const float* c2_wl = (const float*)d_in[7];
    const float* c2_bl = (const float*)d_in[8];
    const float* c2_wr = (const float*)d_in[9];
    const float* p2_wrel = (const float*)d_in[10];
    const float* p2_brel = (const float*)d_in[11];
    const float* p2_wroot = (const float*)d_in[12];
    const float* g_w  = (const float*)d_in[13];
    const float* g_as = (const float*)d_in[14];
    const float* g_ad = (const float*)d_in[15];
    const float* g_we = (const float*)d_in[16];
    const float* g_ae = (const float*)d_in[17];
    const float* g_b  = (const float*)d_in[18];
    const float* p3_wrel = (const float*)d_in[19];
    const float* p3_brel = (const float*)d_in[20];
    const float* p3_wroot = (const float*)d_in[21];
    const float* l1_w = (const float*)d_in[22];
    const float* l1_b = (const float*)d_in[23];
    const float* l2_w = (const float*)d_in[24];
    const float* l2_b = (const float*)d_in[25];
    const float* l3_w = (const float*)d_in[26];
    const float* l3_b = (const float*)d_in[27];
    float* out = (float*)d_out;

    float *px, *py, *pagg, *pg1, *pg2, *pg3, *pxs;
    cudaGetSymbolAddress((void**)&px,  d_x);
    cudaGetSymbolAddress((void**)&py,  d_y);
    cudaGetSymbolAddress((void**)&pagg, d_agg);
    cudaGetSymbolAddress((void**)&pg1, d_g1);
    cudaGetSymbolAddress((void**)&pg2, d_g2);
    cudaGetSymbolAddress((void**)&pg3, d_g3);
    cudaGetSymbolAddress((void**)&pxs, d_xs);
    unsigned char* pwb;
    cudaGetSymbolAddress((void**)&pwb, d_wbf);

    cudaFuncSetAttribute(tgemm_k, cudaFuncAttributeMaxDynamicSharedMemorySize, TGEMM_SMEM);

    const int TB = 256;
    dim3 gE(EE / TB);
    dim3 gW(NBn * 32 / TB);
    dim3 gN(NBn / TB);

    // preprocessing
    init_k<<<gE, TB>>>();
    csr_count_k<<<gE, TB>>>(dstA);
    scan_k<<<1, 512>>>();
    csr_fill_k<<<gE, TB>>>(dstA);
    norm_k<<<1, 128>>>(p1_w);
    prep_w_k<<<320, 256>>>(c1_wl, c1_wr, c2_wl, c2_wr, g_w);

    // ---- block 1: SAGE -> TopK(0.8) -> gap ----
    agg_k<<<gW, TB>>>(x_in, srcA);
    tgemm_k<<<512, 256, TGEMM_SMEM>>>(pagg, pwb + 0, x_in, pwb + 65536, c1_bl, px, 1);
    score1_k<<<gW, TB>>>(p1_w);
    pool_k<<<Bg, 256>>>(KP1);
    apply_pool_k<<<gW, TB>>>(px);
    emf_update_k<<<gE, TB>>>(srcA, dstA);
    gap_k<<<Bg * 4, 128>>>(px, pg1, 1.0f / KP1);

    // ---- block 2: SAGE -> SAGPool(0.5) -> gap ----
    agg_k<<<gW, TB>>>(px, srcA);
    tgemm_k<<<512, 256, TGEMM_SMEM>>>(pagg, pwb + 131072, px, pwb + 196608, c2_bl, py, 1);
    dot2_k<<<gW, TB>>>(py, p2_wrel, p2_wroot);
    sag2b_k<<<gN, TB>>>(srcA, p2_brel);
    pool_k<<<Bg, 256>>>(KP2);
    apply_pool_k<<<gW, TB>>>(py);
    emf_update_k<<<gE, TB>>>(srcA, dstA);
    gap_k<<<Bg * 4, 128>>>(py, pg2, 1.0f / KP2);

    // ---- block 3: GAT -> SAGPool(0.5) -> gap ----
    tgemm_k<<<512, 256, TGEMM_SMEM>>>(py, pwb + 262144, nullptr, nullptr, nullptr, pxs, 0);
    alsald_k<<<gW, TB>>>(g_as, g_ad);
    weeff_k<<<1, 32>>>(g_we, g_ae);
    ale_k<<<gE, TB>>>(ea);
    eamean_k<<<512, 256>>>(ea);
    alse_k<<<1, 4>>>();
    gat_k<<<NBn, 128>>>(srcA, g_b);
    dot2_k<<<gW, TB>>>(px, p3_wrel, p3_wroot);
    sag2b_k<<<gN, TB>>>(srcA, p3_brel);
    pool_k<<<Bg, 256>>>(KP3);
    apply_pool_k<<<gW, TB>>>(px);
    gap_k<<<Bg * 4, 128>>>(px, pg3, 1.0f / KP3);

    // ---- head ----
    mlp_k<<<Bg, 128>>>(l1_w, l1_b, l2_w, l2_b, l3_w, l3_b, out);
}

// round 9
// speedup vs baseline: 1.6420x; 1.6420x over previous
#include <cuda_runtime.h>
#include <cuda_bf16.h>
#include <math.h>
#include <stdint.h>

#define NBn 65536
#define EE  1048576
#define Bg  128
#define Ng  512
#define Fd  128
#define KP1 410
#define KP2 205
#define KP3 103

#define FINF __int_as_float(0x7f800000)

// ================= mma.sync helpers (baseline PTX, no sm_103a features) =================
__device__ __forceinline__ uint32_t smem_u32(const void* p) {
    uint32_t a;
    asm("{ .reg .u64 t; cvta.to.shared.u64 t, %1; cvt.u32.u64 %0, t; }" : "=r"(a) : "l"(p));
    return a;
}
__device__ __forceinline__ void ldsm4(uint32_t a, uint32_t& r0, uint32_t& r1, uint32_t& r2, uint32_t& r3) {
    asm volatile("ldmatrix.sync.aligned.m8n8.x4.shared.b16 {%0,%1,%2,%3}, [%4];"
        : "=r"(r0), "=r"(r1), "=r"(r2), "=r"(r3) : "r"(a));
}
__device__ __forceinline__ void ldsm4t(uint32_t a, uint32_t& r0, uint32_t& r1, uint32_t& r2, uint32_t& r3) {
    asm volatile("ldmatrix.sync.aligned.m8n8.x4.trans.shared.b16 {%0,%1,%2,%3}, [%4];"
        : "=r"(r0), "=r"(r1), "=r"(r2), "=r"(r3) : "r"(a));
}
__device__ __forceinline__ void mma16816(float* d, const uint32_t* a, uint32_t b0, uint32_t b1) {
    asm volatile("mma.sync.aligned.m16n8k16.row.col.f32.bf16.bf16.f32 "
        "{%0,%1,%2,%3},{%4,%5,%6,%7},{%8,%9},{%0,%1,%2,%3};"
        : "+f"(d[0]), "+f"(d[1]), "+f"(d[2]), "+f"(d[3])
        : "r"(a[0]), "r"(a[1]), "r"(a[2]), "r"(a[3]), "r"(b0), "r"(b1));
}

// swizzled smem offset: 128 rows x 16 chunks of 16B (256B/row), XOR swizzle kills bank conflicts
#define SW_OFF(r, c) ((uint32_t)((r) * 256 + ((((c) ^ ((r) & 7))) << 4)))

// ================= device scratch =================
__device__ __align__(16) float d_x[NBn * Fd];
__device__ __align__(16) float d_y[NBn * Fd];
__device__ __align__(16) float d_agg[NBn * Fd];
__device__ __align__(16) float d_xs[NBn * Fd];
__device__ float d_score[NBn];
__device__ float d_nmask[NBn];
__device__ int   d_indeg[NBn];
__device__ int   d_off[NBn + 1];
__device__ int   d_fill[NBn];
__device__ int   d_eid[EE];
__device__ float d_als[NBn * 4];
__device__ float d_ald[NBn * 4];
__device__ float d_ale[EE * 4];
__device__ float d_weeff[28];
__device__ float d_alse[4];
__device__ float d_eamean[8];
__device__ float d_pinv;
__device__ float d_r[NBn];
__device__ float d_q[NBn];
__device__ float d_g1[Bg * Fd];
__device__ float d_g2[Bg * Fd];
__device__ float d_g3[Bg * Fd];
// 5 weight matrices, each: hi bf16 32KB + lo bf16 32KB, SW-swizzled [k][n]
__device__ __align__(16) unsigned char d_wbf[5 * 65536];

// ================= helpers =================
__device__ __forceinline__ float warp_red(float v) {
    #pragma unroll
    for (int o = 16; o; o >>= 1) v += __shfl_down_sync(0xffffffffu, v, o);
    return v;
}

// ================= init =================
__global__ void init_k() {
    int t = blockIdx.x * blockDim.x + threadIdx.x;
    if (t < NBn) { d_nmask[t] = 1.0f; d_indeg[t] = 0; d_fill[t] = 0; }
    if (t < 8) d_eamean[t] = 0.0f;
    if (t < Bg * Fd) { d_g1[t] = 0.f; d_g2[t] = 0.f; d_g3[t] = 0.f; }
}

// ================= CSR build =================
__global__ void csr_count_k(const int* __restrict__ dst) {
    int e = blockIdx.x * blockDim.x + threadIdx.x;
    if (e < EE) atomicAdd(&d_indeg[dst[e]], 1);
}
__global__ void scan_k() {
    __shared__ int tot[512];
    int t = threadIdx.x;
    int base = t * 128;
    int s = 0;
    for (int j = 0; j < 128; j++) { d_off[base + j] = s; s += d_indeg[base + j]; }
    tot[t] = s;
    __syncthreads();
    if (t == 0) {
        int run = 0;
        for (int k = 0; k < 512; k++) { int v = tot[k]; tot[k] = run; run += v; }
        d_off[NBn] = run;
    }
    __syncthreads();
    int add = tot[t];
    for (int j = 0; j < 128; j++) d_off[base + j] += add;
}
__global__ void csr_fill_k(const int* __restrict__ dst) {
    int e = blockIdx.x * blockDim.x + threadIdx.x;
    if (e < EE) {
        int d = dst[e];
        int p = atomicAdd(&d_fill[d], 1);
        d_eid[d_off[d] + p] = e;
    }
}

// ================= p1 norm =================
__global__ void norm_k(const float* __restrict__ pw) {
    __shared__ float r[128];
    int t = threadIdx.x;
    float v = pw[t];
    r[t] = v * v;
    __syncthreads();
    for (int o = 64; o; o >>= 1) { if (t < o) r[t] += r[t + o]; __syncthreads(); }
    if (t == 0) d_pinv = rsqrtf(r[0]);
}

// ================= weight prep: fp32 -> bf16 hi/lo, SW-swizzled [k][n] =================
__global__ void prep_w_k(const float* __restrict__ w0, const float* __restrict__ w1,
                         const float* __restrict__ w2, const float* __restrict__ w3,
                         const float* __restrict__ w4) {
    int id = blockIdx.x * blockDim.x + threadIdx.x;
    if (id >= 5 * 16384) return;
    int m = id >> 14;
    int r = id & 16383;
    int k = r >> 7, n = r & 127;
    const float* W = (m == 0) ? w0 : (m == 1) ? w1 : (m == 2) ? w2 : (m == 3) ? w3 : w4;
    float f = W[k * 128 + n];
    __nv_bfloat16 hb = __float2bfloat16(f);
    __nv_bfloat16 lb = __float2bfloat16(f - __bfloat162float(hb));
    uint32_t off = SW_OFF(k, n >> 3) + (uint32_t)(n & 7) * 2;
    unsigned char* base = d_wbf + m * 65536;
    *(__nv_bfloat16*)(base + off) = hb;
    *(__nv_bfloat16*)(base + 32768 + off) = lb;
}

// ================= HMMA GEMM: C[128x128/CTA] = A1@W1 (+A2@W2) (+bias)(relu) =================
__device__ __forceinline__ void stageA(const float* __restrict__ A, int bm, char* smA, int tid) {
    for (int i = tid; i < 2048; i += 256) {
        int r = i >> 4, c = i & 15;
        const float4* s = (const float4*)(A + (size_t)(bm + r) * 128 + c * 8);
        float4 f0 = s[0], f1 = s[1];
        float v[8] = {f0.x, f0.y, f0.z, f0.w, f1.x, f1.y, f1.z, f1.w};
        __nv_bfloat16 h[8], l[8];
        #pragma unroll
        for (int j = 0; j < 8; j++) {
            h[j] = __float2bfloat16(v[j]);
            l[j] = __float2bfloat16(v[j] - __bfloat162float(h[j]));
        }
        uint32_t off = SW_OFF(r, c);
        *(uint4*)(smA + off) = *(uint4*)h;
        *(uint4*)(smA + 32768 + off) = *(uint4*)l;
    }
}

__device__ __forceinline__ void hmma_pass(uint32_t aS, uint32_t bS, int wm, int wn, int lane,
                                          float acc[4][4][4]) {
    int lr = lane & 15, lc = lane >> 4;
    #pragma unroll
    for (int ks = 0; ks < 8; ks++) {
        uint32_t a[4][4];
        #pragma unroll
        for (int mi = 0; mi < 4; mi++) {
            int row = wm * 64 + mi * 16 + lr;
            int ch = ks * 2 + lc;
            ldsm4(aS + SW_OFF(row, ch), a[mi][0], a[mi][1], a[mi][2], a[mi][3]);
        }
        uint32_t b[2][4];
        #pragma unroll
        for (int nb = 0; nb < 2; nb++) {
            int row = ks * 16 + lr;
            int ch = wn * 4 + nb * 2 + lc;
            ldsm4t(bS + SW_OFF(row, ch), b[nb][0], b[nb][1], b[nb][2], b[nb][3]);
        }
        #pragma unroll
        for (int mi = 0; mi < 4; mi++)
            #pragma unroll
            for (int ni = 0; ni < 4; ni++)
                mma16816(acc[mi][ni], a[mi], b[ni >> 1][(ni & 1) * 2], b[ni >> 1][(ni & 1) * 2 + 1]);
    }
}

__global__ void __launch_bounds__(256, 1) tgemm_k(
    const float* __restrict__ A1, const unsigned char* __restrict__ W1,
    const float* __restrict__ A2, const unsigned char* __restrict__ W2,
    const float* __restrict__ bias, float* __restrict__ C, int relu)
{
    extern __shared__ char sm[];
    uint32_t sb = smem_u32(sm);
    int tid = threadIdx.x, lane = tid & 31, wid = tid >> 5;
    int wm = wid & 1, wn = wid >> 1;
    int bm = blockIdx.x * 128;
    const uint32_t Ahi = sb, Alo = sb + 32768, Whi = sb + 65536, Wlo = sb + 98304;
    float acc[4][4][4] = {};

    // ---- phase 0 ----
    stageA(A1, bm, sm, tid);
    {
        uint4* dW = (uint4*)(sm + 65536);
        const uint4* sW = (const uint4*)W1;
        for (int i = tid; i < 4096; i += 256) dW[i] = sW[i];
    }
    __syncthreads();
    hmma_pass(Ahi, Whi, wm, wn, lane, acc);
    hmma_pass(Ahi, Wlo, wm, wn, lane, acc);
    hmma_pass(Alo, Whi, wm, wn, lane, acc);
    // ---- phase 1 (fused second matmul accumulating into same regs) ----
    if (A2) {
        __syncthreads();
        stageA(A2, bm, sm, tid);
        {
            uint4* dW = (uint4*)(sm + 65536);
            const uint4* sW = (const uint4*)W2;
            for (int i = tid; i < 4096; i += 256) dW[i] = sW[i];
        }
        __syncthreads();
        hmma_pass(Ahi, Whi, wm, wn, lane, acc);
        hmma_pass(Ahi, Wlo, wm, wn, lane, acc);
        hmma_pass(Alo, Whi, wm, wn, lane, acc);
    }

    // ---- epilogue ----
    int group = lane >> 2, tig = lane & 3;
    #pragma unroll
    for (int mi = 0; mi < 4; mi++) {
        int row = bm + wm * 64 + mi * 16 + group;
        #pragma unroll
        for (int ni = 0; ni < 4; ni++) {
            int col = wn * 32 + ni * 8 + tig * 2;
            float b0 = 0.f, b1 = 0.f;
            if (bias) { b0 = bias[col]; b1 = bias[col + 1]; }
            float2 v0 = make_float2(acc[mi][ni][0] + b0, acc[mi][ni][1] + b1);
            float2 v1 = make_float2(acc[mi][ni][2] + b0, acc[mi][ni][3] + b1);
            if (relu) {
                v0.x = fmaxf(v0.x, 0.f); v0.y = fmaxf(v0.y, 0.f);
                v1.x = fmaxf(v1.x, 0.f); v1.y = fmaxf(v1.y, 0.f);
            }
            *(float2*)(C + (size_t)row * 128 + col) = v0;
            *(float2*)(C + (size_t)(row + 8) * 128 + col) = v1;
        }
    }
}
#define TGEMM_SMEM 131072

// ================= segment mean aggregation via CSR (warp per dst), branchless =================
// x rows of inactive nodes are exactly zero (apply_pool), so accumulate unconditionally;
// cnt = sum of nmask[src]. Outputs at inactive dst are unused downstream.
__global__ void agg_k(const float* __restrict__ x, const int* __restrict__ srcA) {
    int warp = (blockIdx.x * blockDim.x + threadIdx.x) >> 5;
    if (warp >= NBn) return;
    int lane = threadIdx.x & 31;
    int beg = d_off[warp], end = d_off[warp + 1];
    float4 acc = make_float4(0.f, 0.f, 0.f, 0.f);
    float cnt = 0.f;
    for (int j = beg; j < end; j++) {
        int e = d_eid[j];
        int s = srcA[e];
        cnt += d_nmask[s];
        float4 v = *reinterpret_cast<const float4*>(x + (size_t)s * Fd + lane * 4);
        acc.x += v.x; acc.y += v.y; acc.z += v.z; acc.w += v.w;
    }
    float inv = 1.f / fmaxf(cnt, 1.f);
    acc.x *= inv; acc.y *= inv; acc.z *= inv; acc.w *= inv;
    *reinterpret_cast<float4*>(d_agg + (size_t)warp * Fd + lane * 4) = acc;
}

// ================= scores =================
__global__ void score1_k(const float* __restrict__ pw) {
    int warp = (blockIdx.x * blockDim.x + threadIdx.x) >> 5;
    if (warp >= NBn) return;
    int lane = threadIdx.x & 31;
    float s = 0.f;
    #pragma unroll
    for (int q = 0; q < 4; q++) {
        int f = lane + 32 * q;
        s += d_x[(size_t)warp * Fd + f] * pw[f];
    }
    s = warp_red(s);
    if (lane == 0) d_score[warp] = tanhf(s * d_pinv);
}

// per-node scalar dots r = nmask * (x.wrel)  [pre-masked],  q = x.wroot
__global__ void dot2_k(const float* __restrict__ x, const float* __restrict__ wrel,
                       const float* __restrict__ wroot) {
    int warp = (blockIdx.x * blockDim.x + threadIdx.x) >> 5;
    if (warp >= NBn) return;
    int lane = threadIdx.x & 31;
    float s1 = 0.f, s2 = 0.f;
    #pragma unroll
    for (int q = 0; q < 4; q++) {
        int f = lane + 32 * q;
        float v = x[(size_t)warp * Fd + f];
        s1 += v * wrel[f];
        s2 += v * wroot[f];
    }
    s1 = warp_red(s1); s2 = warp_red(s2);
    if (lane == 0) { d_r[warp] = s1 * d_nmask[warp]; d_q[warp] = s2; }
}

// branchless scalar CSR aggregation for SAG score (thread per dst); r pre-masked
__global__ void sag2b_k(const int* __restrict__ srcA, const float* __restrict__ brel) {
    int i = blockIdx.x * blockDim.x + threadIdx.x;
    if (i >= NBn) return;
    int beg = d_off[i], end = d_off[i + 1];
    float s = 0.f;
    for (int j = beg; j < end; j++) s += d_r[srcA[d_eid[j]]];
    d_score[i] = tanhf(s + d_q[i] + brel[0]);
}

// ================= top-K pooling =================
__global__ void pool_k(int K) {
    __shared__ float sv[512];
    __shared__ short si[512];
    int g = blockIdx.x, t = threadIdx.x;
    for (int p = t; p < 512; p += 256) {
        int node = g * Ng + p;
        sv[p] = (d_nmask[node] != 0.f) ? d_score[node] : -FINF;
        si[p] = (short)p;
    }
    __syncthreads();
    for (int k = 2; k <= 512; k <<= 1) {
        for (int j = k >> 1; j > 0; j >>= 1) {
            for (int p = t; p < 512; p += 256) {
                int ixj = p ^ j;
                if (ixj > p) {
                    float v1 = sv[p], v2 = sv[ixj];
                    short i1 = si[p], i2 = si[ixj];
                    bool beforePI = (v1 > v2) || (v1 == v2 && i1 < i2);
                    bool dir = ((p & k) == 0);
                    if (dir ? !beforePI : beforePI) {
                        sv[p] = v2; sv[ixj] = v1;
                        si[p] = i2; si[ixj] = i1;
                    }
                }
            }
            __syncthreads();
        }
    }
    for (int p = t; p < 512; p += 256)
        d_nmask[g * Ng + si[p]] = (p < K) ? 1.f : 0.f;
}

__global__ void apply_pool_k(float* __restrict__ x) {
    int id = blockIdx.x * blockDim.x + threadIdx.x;
    int node = id >> 5, q = id & 31;
    float sc = d_nmask[node] * d_score[node];
    float4* p = reinterpret_cast<float4*>(x + (size_t)node * Fd + q * 4);
    float4 v = *p;
    v.x *= sc; v.y *= sc; v.z *= sc; v.w *= sc;
    *p = v;
}

__global__ void gap_k(const float* __restrict__ x, float* __restrict__ outg, float invK) {
    int b = blockIdx.x;                  // Bg*4 blocks x 128 threads
    int g = b >> 2, part = b & 3, f = threadIdx.x;
    float s = 0.f;
    int base = g * Ng + part * 128;
    for (int n = 0; n < 128; n++) s += x[(size_t)(base + n) * Fd + f];
    atomicAdd(&outg[g * Fd + f], s * invK);
}

// ================= GAT =================
__global__ void alsald_k(const float* __restrict__ as_, const float* __restrict__ ad_) {
    int warp = (blockIdx.x * blockDim.x + threadIdx.x) >> 5;
    if (warp >= NBn) return;
    int lane = threadIdx.x & 31;
    #pragma unroll
    for (int h = 0; h < 4; h++) {
        float v = d_xs[(size_t)warp * Fd + h * 32 + lane];
        float ps = v * as_[h * 32 + lane];
        float pd = v * ad_[h * 32 + lane];
        ps = warp_red(ps); pd = warp_red(pd);
        if (lane == 0) { d_als[warp * 4 + h] = ps; d_ald[warp * 4 + h] = pd; }
    }
}

__global__ void weeff_k(const float* __restrict__ g_we, const float* __restrict__ a_e) {
    int t = threadIdx.x;
    if (t < 28) {
        int d = t >> 2, h = t & 3;
        float s = 0.f;
        for (int c = 0; c < 32; c++) s += g_we[d * 128 + h * 32 + c] * a_e[h * 32 + c];
        d_weeff[d * 4 + h] = s;
    }
}

__global__ void ale_k(const float* __restrict__ ea) {
    int e = blockIdx.x * blockDim.x + threadIdx.x;
    if (e >= EE) return;
    float a[7];
    #pragma unroll
    for (int d = 0; d < 7; d++) a[d] = ea[(size_t)e * 7 + d];
    #pragma unroll
    for (int h = 0; h < 4; h++) {
        float s = 0.f;
        #pragma unroll
        for (int d = 0; d < 7; d++) s += a[d] * d_weeff[d * 4 + h];
        d_ale[(size_t)e * 4 + h] = s;
    }
}

__global__ void eamean_k(const float* __restrict__ ea, const int* __restrict__ srcA,
                         const int* __restrict__ dstA) {
    __shared__ float red[256 * 8];
    int t = threadIdx.x;
    float acc[7] = {}; float c = 0.f;
    for (int e = blockIdx.x * 256 + t; e < EE; e += gridDim.x * 256) {
        float m = d_nmask[srcA[e]] * d_nmask[dstA[e]];
        if (m != 0.f) {
            #pragma unroll
            for (int d = 0; d < 7; d++) acc[d] += ea[(size_t)e * 7 + d];
            c += 1.f;
        }
    }
    #pragma unroll
    for (int d = 0; d < 7; d++) red[t * 8 + d] = acc[d];
    red[t * 8 + 7] = c;
    __syncthreads();
    if (t < 8) {
        float s = 0.f;
        for (int j = 0; j < 256; j++) s += red[j * 8 + t];
        atomicAdd(&d_eamean[t], s);
    }
}

__global__ void alse_k() {
    int h = threadIdx.x;
    if (h < 4) {
        float cnt = fmaxf(d_eamean[7], 1.f);
        float s = 0.f;
        for (int d = 0; d < 7; d++) s += (d_eamean[d] / cnt) * d_weeff[d * 4 + h];
        d_alse[h] = s;
    }
}

__device__ __forceinline__ float lrelu(float a) { return a > 0.f ? a : 0.2f * a; }

__global__ void gat_k(const int* __restrict__ srcA, const float* __restrict__ gb) {
    int i = blockIdx.x, t = threadIdx.x;
    __shared__ float sm[4], sden[4];
    __shared__ float red[128 * 4];
    __shared__ float s_w[32 * 4];
    __shared__ int s_src[32];
    __shared__ float s_ald[4], s_alsi[4];
    int beg = d_off[i], end = d_off[i + 1];
    if (t < 4) { s_ald[t] = d_ald[i * 4 + t]; s_alsi[t] = d_als[i * 4 + t]; }
    __syncthreads();
    float mx0 = -FINF, mx1 = -FINF, mx2 = -FINF, mx3 = -FINF;
    for (int j = beg + t; j < end; j += 128) {
        int e = d_eid[j];
        int s = srcA[e];
        if (d_nmask[s] != 0.f) {
            mx0 = fmaxf(mx0, lrelu(d_als[s * 4 + 0] + s_ald[0] + d_ale[(size_t)e * 4 + 0]));
            mx1 = fmaxf(mx1, lrelu(d_als[s * 4 + 1] + s_ald[1] + d_ale[(size_t)e * 4 + 1]));
            mx2 = fmaxf(mx2, lrelu(d_als[s * 4 + 2] + s_ald[2] + d_ale[(size_t)e * 4 + 2]));
            mx3 = fmaxf(mx3, lrelu(d_als[s * 4 + 3] + s_ald[3] + d_ale[(size_t)e * 4 + 3]));
        }
    }
    red[t * 4 + 0] = mx0; red[t * 4 + 1] = mx1; red[t * 4 + 2] = mx2; red[t * 4 + 3] = mx3;
    __syncthreads();
    if (t < 4) {
        float m = -FINF;
        for (int j = 0; j < 128; j++) m = fmaxf(m, red[j * 4 + t]);
        if (d_nmask[i] != 0.f)
            m = fmaxf(m, lrelu(s_alsi[t] + s_ald[t] + d_alse[t]));
        if (!isfinite(m)) m = 0.f;
        sm[t] = m; sden[t] = 0.f;
    }
    __syncthreads();
    float acc = 0.f;
    int h = t >> 5;
    for (int cb = beg; cb < end; cb += 32) {
        int n = min(32, end - cb);
        int jl = t >> 2, hh = t & 3;
        if (jl < n) {
            int e = d_eid[cb + jl];
            int s = srcA[e];
            if (hh == 0) s_src[jl] = s;
            float w = 0.f;
            if (d_nmask[s] != 0.f) {
                float a = lrelu(d_als[s * 4 + hh] + s_ald[hh] + d_ale[(size_t)e * 4 + hh]);
                w = __expf(a - sm[hh]);
            }
            s_w[jl * 4 + hh] = w;
        }
        __syncthreads();
        if (t < 4) {
            float s = 0.f;
            for (int j = 0; j < n; j++) s += s_w[j * 4 + t];
            sden[t] += s;
        }
        for (int j = 0; j < n; j++)
            acc += s_w[j * 4 + h] * d_xs[(size_t)s_src[j] * Fd + t];
        __syncthreads();
    }
    if (d_nmask[i] != 0.f) {
        float a = lrelu(s_alsi[h] + s_ald[h] + d_alse[h]);
        acc += __expf(a - sm[h]) * d_xs[(size_t)i * Fd + t];
        if (t < 4) {
            float a4 = lrelu(s_alsi[t] + s_ald[t] + d_alse[t]);
            sden[t] += __expf(a4 - sm[t]);
        }
    }
    __syncthreads();
    float den = fmaxf(sden[h], 1e-16f);
    d_x[(size_t)i * Fd + t] = fmaxf(acc / den + gb[t], 0.f);
}

// ================= final MLP head =================
__global__ void mlp_k(const float* __restrict__ l1w, const float* __restrict__ l1b,
                      const float* __restrict__ l2w, const float* __restrict__ l2b,
                      const float* __restrict__ l3w, const float* __restrict__ l3b,
                      float* __restrict__ out) {
    int g = blockIdx.x, t = threadIdx.x;
    __shared__ float h0[128], t1[128], t2[64], rr[64];
    h0[t] = d_g1[g * Fd + t] + d_g2[g * Fd + t] + d_g3[g * Fd + t];
    __syncthreads();
    float s = 0.f;
    for (int k = 0; k < 128; k++) s += h0[k] * l1w[k * 128 + t];
    t1[t] = fmaxf(s + l1b[t], 0.f);
    __syncthreads();
    if (t < 64) {
        float s2 = 0.f;
        for (int k = 0; k < 128; k++) s2 += t1[k] * l2w[k * 64 + t];
        t2[t] = fmaxf(s2 + l2b[t], 0.f);
        rr[t] = 0.f;
    }
    __syncthreads();
    if (t < 64) rr[t] = t2[t] * l3w[t];
    __syncthreads();
    for (int o = 32; o; o >>= 1) { if (t < o) rr[t] += rr[t + o]; __syncthreads(); }
    if (t == 0) out[g] = 1.f / (1.f + expf(-(rr[0] + l3b[0])));
}

// ================= host =================
extern "C" void kernel_launch(void* const* d_in, const int* in_sizes, int n_in,
                              void* d_out, int out_size) {
    const float* x_in  = (const float*)d_in[0];
    const int*   ei    = (const int*)d_in[1];
    const int*   srcA  = ei;
    const int*   dstA  = ei + EE;
    const float* ea    = (const float*)d_in[2];
    const float* c1_wl = (const float*)d_in[3];
    const float* c1_bl = (const float*)d_in[4];
    const float* c1_wr = (const float*)d_in[5];
    const float* p1_w  = (const float*)d_in[6];
    const float* c2_wl = (const float*)d_in[7];
    const float* c2_bl = (const float*)d_in[8];
    const float* c2_wr = (const float*)d_in[9];
    const float* p2_wrel = (const float*)d_in[10];
    const float* p2_brel = (const float*)d_in[11];
    const float* p2_wroot = (const float*)d_in[12];
    const float* g_w  = (const float*)d_in[13];
    const float* g_as = (const float*)d_in[14];
    const float* g_ad = (const float*)d_in[15];
    const float* g_we = (const float*)d_in[16];
    const float* g_ae = (const float*)d_in[17];
    const float* g_b  = (const float*)d_in[18];
    const float* p3_wrel = (const float*)d_in[19];
    const float* p3_brel = (const float*)d_in[20];
    const float* p3_wroot = (const float*)d_in[21];
    const float* l1_w = (const float*)d_in[22];
    const float* l1_b = (const float*)d_in[23];
    const float* l2_w = (const float*)d_in[24];
    const float* l2_b = (const float*)d_in[25];
    const float* l3_w = (const float*)d_in[26];
    const float* l3_b = (const float*)d_in[27];
    float* out = (float*)d_out;

    float *px, *py, *pagg, *pg1, *pg2, *pg3, *pxs;
    cudaGetSymbolAddress((void**)&px,  d_x);
    cudaGetSymbolAddress((void**)&py,  d_y);
    cudaGetSymbolAddress((void**)&pagg, d_agg);
    cudaGetSymbolAddress((void**)&pg1, d_g1);
    cudaGetSymbolAddress((void**)&pg2, d_g2);
    cudaGetSymbolAddress((void**)&pg3, d_g3);
    cudaGetSymbolAddress((void**)&pxs, d_xs);
    unsigned char* pwb;
    cudaGetSymbolAddress((void**)&pwb, d_wbf);

    cudaFuncSetAttribute(tgemm_k, cudaFuncAttributeMaxDynamicSharedMemorySize, TGEMM_SMEM);

    const int TB = 256;
    dim3 gE(EE / TB);
    dim3 gW(NBn * 32 / TB);
    dim3 gN(NBn / TB);

    // preprocessing
    init_k<<<gN, TB>>>();
    csr_count_k<<<gE, TB>>>(dstA);
    scan_k<<<1, 512>>>();
    csr_fill_k<<<gE, TB>>>(dstA);
    norm_k<<<1, 128>>>(p1_w);
    prep_w_k<<<320, 256>>>(c1_wl, c1_wr, c2_wl, c2_wr, g_w);

    // ---- block 1: SAGE -> TopK(0.8) -> gap ----
    agg_k<<<gW, TB>>>(x_in, srcA);
    tgemm_k<<<512, 256, TGEMM_SMEM>>>(pagg, pwb + 0, x_in, pwb + 65536, c1_bl, px, 1);
    score1_k<<<gW, TB>>>(p1_w);
    pool_k<<<Bg, 256>>>(KP1);
    apply_pool_k<<<gW, TB>>>(px);
    gap_k<<<Bg * 4, 128>>>(px, pg1, 1.0f / KP1);

    // ---- block 2: SAGE -> SAGPool(0.5) -> gap ----
    agg_k<<<gW, TB>>>(px, srcA);
    tgemm_k<<<512, 256, TGEMM_SMEM>>>(pagg, pwb + 131072, px, pwb + 196608, c2_bl, py, 1);
    dot2_k<<<gW, TB>>>(py, p2_wrel, p2_wroot);
    sag2b_k<<<gN, TB>>>(srcA, p2_brel);
    pool_k<<<Bg, 256>>>(KP2);
    apply_pool_k<<<gW, TB>>>(py);
    gap_k<<<Bg * 4, 128>>>(py, pg2, 1.0f / KP2);

    // ---- block 3: GAT -> SAGPool(0.5) -> gap ----
    tgemm_k<<<512, 256, TGEMM_SMEM>>>(py, pwb + 262144, nullptr, nullptr, nullptr, pxs, 0);
    alsald_k<<<gW, TB>>>(g_as, g_ad);
    weeff_k<<<1, 32>>>(g_we, g_ae);
    ale_k<<<gE, TB>>>(ea);
    eamean_k<<<512, 256>>>(ea, srcA, dstA);
    alse_k<<<1, 4>>>();
    gat_k<<<NBn, 128>>>(srcA, g_b);
    dot2_k<<<gW, TB>>>(px, p3_wrel, p3_wroot);
    sag2b_k<<<gN, TB>>>(srcA, p3_brel);
    pool_k<<<Bg, 256>>>(KP3);
    apply_pool_k<<<gW, TB>>>(px);
    gap_k<<<Bg * 4, 128>>>(px, pg3, 1.0f / KP3);

    // ---- head ----
    mlp_k<<<Bg, 128>>>(l1_w, l1_b, l2_w, l2_b, l3_w, l3_b, out);
}